// round 1
// baseline (speedup 1.0000x reference)
#include <cuda_runtime.h>
#include <math.h>

// Problem-fixed capacities (dataset constants)
#define NCAP 100000
#define ECAP 1600000
#define ITERS 5

struct __align__(8) EdgeRec { int src; float w; };

// ---- static device scratch (no allocation allowed) ----
__device__ int     g_counts[NCAP];
__device__ int     g_rowoff[NCAP + 1];
__device__ int     g_bsums[1024];
__device__ float   g_dis[NCAP];
__device__ EdgeRec g_edges[ECAP];
__device__ float   g_aggx[NCAP * 3];
// float4-typed to guarantee 16B alignment for vector loads
__device__ float4  g_t[NCAP * 16];
__device__ float4  g_u[NCAP * 16];
__device__ float4  g_v[NCAP * 16];

// =============== graph setup kernels ===============

__global__ void k_count(const int* __restrict__ dst, int E, int* __restrict__ counts) {
    int i = blockIdx.x * blockDim.x + threadIdx.x;
    if (i < E) atomicAdd(&counts[dst[i]], 1);
}

__global__ void k_dis(const int* __restrict__ counts, float* __restrict__ dis, int N) {
    int i = blockIdx.x * blockDim.x + threadIdx.x;
    if (i < N) dis[i] = rsqrtf((float)(counts[i] + 1));   // +1 self loop, deg >= 1
}

// exclusive scan of counts -> rowoff, 3-phase
__global__ void k_scan1(const int* __restrict__ counts, int* __restrict__ out,
                        int* __restrict__ bsums, int n) {
    __shared__ int s[512];
    int tid = threadIdx.x;
    int i = blockIdx.x * 512 + tid;
    int v = (i < n) ? counts[i] : 0;
    s[tid] = v;
    __syncthreads();
    for (int off = 1; off < 512; off <<= 1) {
        int t = 0;
        if (tid >= off) t = s[tid - off];
        __syncthreads();
        s[tid] += t;
        __syncthreads();
    }
    if (i < n) out[i] = s[tid] - v;           // exclusive
    if (tid == 511) bsums[blockIdx.x] = s[511];
}

__global__ void k_scan2(int* __restrict__ bsums, int nb) {
    __shared__ int s[256];
    int tid = threadIdx.x;
    int v = (tid < nb) ? bsums[tid] : 0;
    s[tid] = v;
    __syncthreads();
    for (int off = 1; off < 256; off <<= 1) {
        int t = 0;
        if (tid >= off) t = s[tid - off];
        __syncthreads();
        s[tid] += t;
        __syncthreads();
    }
    if (tid < nb) bsums[tid] = s[tid] - v;    // exclusive block offsets
}

__global__ void k_scan3(int* __restrict__ out, const int* __restrict__ bsums, int n, int E) {
    int i = blockIdx.x * 512 + threadIdx.x;
    if (i < n) out[i] += bsums[blockIdx.x];
    if (i == 0) out[n] = E;
}

__global__ void k_fill(const int* __restrict__ srcA, const int* __restrict__ dstA, int E,
                       const int* __restrict__ rowoff, int* __restrict__ cursor,
                       const float* __restrict__ dis, EdgeRec* __restrict__ edges) {
    int i = blockIdx.x * blockDim.x + threadIdx.x;
    if (i >= E) return;
    int s = srcA[i], d = dstA[i];
    int pos = rowoff[d] + atomicAdd(&cursor[d], 1);
    EdgeRec r;
    r.src = s;
    r.w = dis[s] * dis[d];
    edges[pos] = r;
}

// =============== aggregation kernels ===============

// width-64: warp per node, float2 per lane
__global__ void k_agg64(const float* __restrict__ u, const EdgeRec* __restrict__ edges,
                        const int* __restrict__ rowoff, const float* __restrict__ dis,
                        const float* __restrict__ bias, const float* __restrict__ res,
                        int relu, float* __restrict__ out, int N) {
    int node = blockIdx.x * 8 + (threadIdx.x >> 5);
    int lane = threadIdx.x & 31;
    if (node >= N) return;
    const float2* U = (const float2*)u;
    float2 acc = make_float2(0.f, 0.f);
    int e0 = rowoff[node], e1 = rowoff[node + 1];
    for (int e = e0; e < e1; e++) {
        EdgeRec r = edges[e];
        float2 f = U[(size_t)r.src * 32 + lane];
        acc.x = fmaf(r.w, f.x, acc.x);
        acc.y = fmaf(r.w, f.y, acc.y);
    }
    float dv = dis[node];
    float sw = dv * dv;
    float2 f = U[(size_t)node * 32 + lane];
    acc.x = fmaf(sw, f.x, acc.x);
    acc.y = fmaf(sw, f.y, acc.y);
    if (bias) {
        float2 b = ((const float2*)bias)[lane];
        acc.x += b.x; acc.y += b.y;
    }
    if (res) {
        float2 rr = ((const float2*)res)[(size_t)node * 32 + lane];
        acc.x += rr.x; acc.y += rr.y;
    }
    if (relu) {
        acc.x = fmaxf(acc.x, 0.f);
        acc.y = fmaxf(acc.y, 0.f);
    }
    ((float2*)out)[(size_t)node * 32 + lane] = acc;
}

// width-32: warp per node, 1 float per lane
__global__ void k_agg32(const float* __restrict__ u, const EdgeRec* __restrict__ edges,
                        const int* __restrict__ rowoff, const float* __restrict__ dis,
                        const float* __restrict__ bias, int relu,
                        float* __restrict__ out, int N) {
    int node = blockIdx.x * 8 + (threadIdx.x >> 5);
    int lane = threadIdx.x & 31;
    if (node >= N) return;
    float acc = 0.f;
    int e0 = rowoff[node], e1 = rowoff[node + 1];
    for (int e = e0; e < e1; e++) {
        EdgeRec r = edges[e];
        acc = fmaf(r.w, u[(size_t)r.src * 32 + lane], acc);
    }
    float dv = dis[node];
    acc = fmaf(dv * dv, u[(size_t)node * 32 + lane], acc);
    if (bias) acc += bias[lane];
    if (relu) acc = fmaxf(acc, 0.f);
    out[(size_t)node * 32 + lane] = acc;
}

// small widths (2,3,8): thread per node
template <int W>
__global__ void k_agg_t(const float* __restrict__ u, const EdgeRec* __restrict__ edges,
                        const int* __restrict__ rowoff, const float* __restrict__ dis,
                        const float* __restrict__ bias, int relu,
                        float* __restrict__ out, int N) {
    int node = blockIdx.x * blockDim.x + threadIdx.x;
    if (node >= N) return;
    float acc[W];
#pragma unroll
    for (int k = 0; k < W; k++) acc[k] = 0.f;
    int e0 = rowoff[node], e1 = rowoff[node + 1];
    for (int e = e0; e < e1; e++) {
        EdgeRec r = edges[e];
        const float* up = u + (size_t)r.src * W;
#pragma unroll
        for (int k = 0; k < W; k++) acc[k] = fmaf(r.w, __ldg(up + k), acc[k]);
    }
    float dv = dis[node];
    float sw = dv * dv;
    const float* us = u + (size_t)node * W;
#pragma unroll
    for (int k = 0; k < W; k++) acc[k] = fmaf(sw, us[k], acc[k]);
    if (bias) {
#pragma unroll
        for (int k = 0; k < W; k++) acc[k] += bias[k];
    }
    if (relu) {
#pragma unroll
        for (int k = 0; k < W; k++) acc[k] = fmaxf(acc[k], 0.f);
    }
#pragma unroll
    for (int k = 0; k < W; k++) out[(size_t)node * W + k] = acc[k];
}

// =============== dense kernels ===============

// projection: t = relu(aggx @ Wp + bp), Wp [3,64]
__global__ void k_proj(const float* __restrict__ aggx, const float* __restrict__ Wp,
                       const float* __restrict__ bp, float* __restrict__ t, int N) {
    int node = blockIdx.x * 4 + (threadIdx.x >> 6);
    int j = threadIdx.x & 63;
    if (node >= N) return;
    float a0 = aggx[node * 3], a1 = aggx[node * 3 + 1], a2 = aggx[node * 3 + 2];
    float acc = bp[j];
    acc = fmaf(a0, Wp[j], acc);
    acc = fmaf(a1, Wp[64 + j], acc);
    acc = fmaf(a2, Wp[128 + j], acc);
    t[(size_t)node * 64 + j] = fmaxf(acc, 0.f);
}

// main matmul: C[N,64] = A[N,64] @ W[64,64]; optional recall epilogue
//   + aggx[N,3] @ Wx[3,64] + br[64]
// tile: 96 rows x 64 cols per block, 96 threads, 8x8 per thread
__global__ void k_mm96(const float* __restrict__ A, const float* __restrict__ W,
                       const float* __restrict__ Wx, const float* __restrict__ brv,
                       const float* __restrict__ aggx, float* __restrict__ C, int N) {
    __shared__ float As[96][65];
    __shared__ float Ws[64][64];
    int tid = threadIdx.x;
    int row0 = blockIdx.x * 96;
    {
        const float4* Wv = (const float4*)W;
        float4* Wsv = (float4*)Ws;
        for (int i = tid; i < 1024; i += 96) Wsv[i] = Wv[i];
    }
    for (int i = tid; i < 96 * 16; i += 96) {
        int r = i >> 4, kq = i & 15;
        int row = row0 + r;
        float4 v = make_float4(0.f, 0.f, 0.f, 0.f);
        if (row < N) v = ((const float4*)A)[(size_t)row * 16 + kq];
        As[r][kq * 4 + 0] = v.x;
        As[r][kq * 4 + 1] = v.y;
        As[r][kq * 4 + 2] = v.z;
        As[r][kq * 4 + 3] = v.w;
    }
    __syncthreads();

    int tx = tid & 7, ty = tid >> 3;   // tx: col octet, ty: row octet (0..11)
    float acc[8][8];
#pragma unroll
    for (int i = 0; i < 8; i++)
#pragma unroll
        for (int j = 0; j < 8; j++) acc[i][j] = 0.f;

#pragma unroll 8
    for (int k = 0; k < 64; k++) {
        float a[8];
#pragma unroll
        for (int i = 0; i < 8; i++) a[i] = As[ty * 8 + i][k];
        float4 w0 = *(const float4*)&Ws[k][tx * 8];
        float4 w1 = *(const float4*)&Ws[k][tx * 8 + 4];
        float wv[8] = {w0.x, w0.y, w0.z, w0.w, w1.x, w1.y, w1.z, w1.w};
#pragma unroll
        for (int i = 0; i < 8; i++)
#pragma unroll
            for (int j = 0; j < 8; j++) acc[i][j] = fmaf(a[i], wv[j], acc[i][j]);
    }

    bool recall = (aggx != nullptr);
    float wxr[3][8], brr[8];
    if (recall) {
#pragma unroll
        for (int j = 0; j < 8; j++) {
            int col = tx * 8 + j;
            wxr[0][j] = Wx[col];
            wxr[1][j] = Wx[64 + col];
            wxr[2][j] = Wx[128 + col];
            brr[j] = brv[col];
        }
    }
#pragma unroll
    for (int i = 0; i < 8; i++) {
        int row = row0 + ty * 8 + i;
        if (row >= N) continue;
        if (recall) {
            float a0 = aggx[row * 3], a1 = aggx[row * 3 + 1], a2 = aggx[row * 3 + 2];
#pragma unroll
            for (int j = 0; j < 8; j++) {
                acc[i][j] += fmaf(a0, wxr[0][j],
                              fmaf(a1, wxr[1][j], fmaf(a2, wxr[2][j], brr[j])));
            }
        }
        float4 o0 = make_float4(acc[i][0], acc[i][1], acc[i][2], acc[i][3]);
        float4 o1 = make_float4(acc[i][4], acc[i][5], acc[i][6], acc[i][7]);
        ((float4*)C)[(size_t)row * 16 + tx * 2 + 0] = o0;
        ((float4*)C)[(size_t)row * 16 + tx * 2 + 1] = o1;
    }
}

// small head matmuls: warp per node
template <int FIN, int FOUT>
__global__ void k_mm_small(const float* __restrict__ A, const float* __restrict__ W,
                           float* __restrict__ C, int N) {
    __shared__ float Ws[FIN * FOUT + 32];
    int tid = threadIdx.x;
    for (int i = tid; i < FIN * FOUT; i += blockDim.x) Ws[i] = W[i];
    for (int i = FIN * FOUT + tid; i < FIN * FOUT + 32; i += blockDim.x) Ws[i] = 0.f;
    __syncthreads();
    int node = blockIdx.x * 4 + (tid >> 5);
    int j = tid & 31;
    if (node >= N) return;
    float acc = 0.f;
    const float* a = A + (size_t)node * FIN;
#pragma unroll
    for (int k = 0; k < FIN; k++) {
        float av = __ldg(a + k);
        acc = fmaf(av, Ws[k * FOUT + j], acc);
    }
    if (j < FOUT) C[(size_t)node * FOUT + j] = acc;
}

// =============== host launch ===============

extern "C" void kernel_launch(void* const* d_in, const int* in_sizes, int n_in,
                              void* d_out, int out_size) {
    const float* x   = (const float*)d_in[0];
    const float* Wp  = (const float*)d_in[1];
    const float* bp  = (const float*)d_in[2];
    const float* Wr  = (const float*)d_in[3];
    const float* br  = (const float*)d_in[4];
    const float* W11 = (const float*)d_in[5];
    const float* b11 = (const float*)d_in[6];
    const float* W12 = (const float*)d_in[7];
    const float* b12 = (const float*)d_in[8];
    const float* W21 = (const float*)d_in[9];
    const float* b21 = (const float*)d_in[10];
    const float* W22 = (const float*)d_in[11];
    const float* b22 = (const float*)d_in[12];
    const float* Wh1 = (const float*)d_in[13];
    const float* bh1 = (const float*)d_in[14];
    const float* Wh2 = (const float*)d_in[15];
    const float* bh2 = (const float*)d_in[16];
    const float* Wh3 = (const float*)d_in[17];
    const float* bh3 = (const float*)d_in[18];
    const int*   ei  = (const int*)d_in[19];

    int N = in_sizes[0] / 3;
    int E = in_sizes[19] / 2;
    const int* esrc = ei;
    const int* edst = ei + E;

    int *counts, *rowoff, *bsums;
    float *dis, *aggx;
    EdgeRec* edges;
    float4 *t4, *u4, *v4;
    cudaGetSymbolAddress((void**)&counts, g_counts);
    cudaGetSymbolAddress((void**)&rowoff, g_rowoff);
    cudaGetSymbolAddress((void**)&bsums, g_bsums);
    cudaGetSymbolAddress((void**)&dis, g_dis);
    cudaGetSymbolAddress((void**)&edges, g_edges);
    cudaGetSymbolAddress((void**)&aggx, g_aggx);
    cudaGetSymbolAddress((void**)&t4, g_t);
    cudaGetSymbolAddress((void**)&u4, g_u);
    cudaGetSymbolAddress((void**)&v4, g_v);
    float* t = (float*)t4;
    float* u = (float*)u4;
    float* v = (float*)v4;

    int nbE = (E + 255) / 256;
    int nbN = (N + 255) / 256;
    int nbScan = (N + 511) / 512;
    int nbWarp = (N + 7) / 8;       // 8 nodes per 256-thread block
    int nbMM = (N + 95) / 96;
    int nbW4 = (N + 3) / 4;         // 4 nodes per 128/256-thread block

    // ---- graph setup ----
    cudaMemsetAsync(counts, 0, (size_t)N * sizeof(int), 0);
    k_count<<<nbE, 256>>>(edst, E, counts);
    k_dis<<<nbN, 256>>>(counts, dis, N);
    k_scan1<<<nbScan, 512>>>(counts, rowoff, bsums, N);
    k_scan2<<<1, 256>>>(bsums, nbScan);
    k_scan3<<<nbScan, 512>>>(rowoff, bsums, N, E);
    cudaMemsetAsync(counts, 0, (size_t)N * sizeof(int), 0);
    k_fill<<<nbE, 256>>>(esrc, edst, E, rowoff, counts, dis, edges);

    // ---- loop-invariant: agg(x) and projection ----
    k_agg_t<3><<<nbN, 256>>>(x, edges, rowoff, dis, nullptr, 0, aggx, N);
    k_proj<<<nbW4, 256>>>(aggx, Wp, bp, t, N);

    const float* Wrx = Wr + 64 * 64;  // rows 64..66 of Wr (x part)

    // ---- iterations ----
    for (int it = 0; it < ITERS; it++) {
        // recall: t = agg(t) @ Wr_t + aggx @ Wr_x + br
        k_agg64<<<nbWarp, 256>>>(t, edges, rowoff, dis, nullptr, nullptr, 0, v, N);
        k_mm96<<<nbMM, 96>>>(v, Wr, Wrx, br, aggx, t, N);
        // block 1
        k_mm96<<<nbMM, 96>>>(t, W11, nullptr, nullptr, nullptr, u, N);
        k_agg64<<<nbWarp, 256>>>(u, edges, rowoff, dis, b11, nullptr, 1, v, N);
        k_mm96<<<nbMM, 96>>>(v, W12, nullptr, nullptr, nullptr, u, N);
        k_agg64<<<nbWarp, 256>>>(u, edges, rowoff, dis, b12, t, 1, t, N);
        // block 2
        k_mm96<<<nbMM, 96>>>(t, W21, nullptr, nullptr, nullptr, u, N);
        k_agg64<<<nbWarp, 256>>>(u, edges, rowoff, dis, b21, nullptr, 1, v, N);
        k_mm96<<<nbMM, 96>>>(v, W22, nullptr, nullptr, nullptr, u, N);
        k_agg64<<<nbWarp, 256>>>(u, edges, rowoff, dis, b22, t, 1, t, N);
    }

    // ---- head ----
    k_mm_small<64, 32><<<nbW4, 128>>>(t, Wh1, u, N);
    k_agg32<<<nbWarp, 256>>>(u, edges, rowoff, dis, bh1, 1, v, N);
    k_mm_small<32, 8><<<nbW4, 128>>>(v, Wh2, u, N);
    k_agg_t<8><<<nbN, 256>>>(u, edges, rowoff, dis, bh2, 1, v, N);
    k_mm_small<8, 2><<<nbW4, 128>>>(v, Wh3, u, N);
    k_agg_t<2><<<nbN, 256>>>(u, edges, rowoff, dis, bh3, 0, (float*)d_out, N);
}